// round 7
// baseline (speedup 1.0000x reference)
#include <cuda_runtime.h>

#define CNUM 19
#define HWD (512*512)
#define BATCH 8
#define NPIX (BATCH*HWD)
#define NP4 (NPIX/4)                 // 2,097,152/4 = 524,288
#define CH4 (HWD/4)                  // 65,536 = 2^16 (channel stride in float4)
#define NBINS (CNUM*CNUM)            // 361
#define INP_ELEMS (BATCH*CNUM*HWD)   // 39,845,888

__global__ void zero_out_kernel(float* __restrict__ out)
{
    int i = blockIdx.x * blockDim.x + threadIdx.x;
    if (i < NBINS) out[i] = 0.0f;
}

__global__ void __launch_bounds__(256)
confmat_kernel(const float* __restrict__ inp,
               const int*   __restrict__ tgt,
               float*       __restrict__ out)
{
    __shared__ int hist[NBINS];
    for (int i = threadIdx.x; i < NBINS; i += blockDim.x) hist[i] = 0;
    __syncthreads();

    // One float4 pixel-group per thread; grid exactly covers NP4.
    const int p4 = blockIdx.x * blockDim.x + threadIdx.x;   // 0 .. NP4-1
    {
        const int b   = p4 >> 16;          // p4 / CH4   (CH4 = 2^16)
        const int hw4 = p4 & (CH4 - 1);    // p4 % CH4
        const float4* base = reinterpret_cast<const float4*>(inp)
                             + (long long)b * (CNUM * CH4) + hw4;

        float4 m = __ldg(&base[0]);
        int ax = 0, ay = 0, az = 0, aw = 0;
        #pragma unroll
        for (int c = 1; c < CNUM; c++) {
            float4 v = __ldg(&base[c * CH4]);
            if (v.x > m.x) { m.x = v.x; ax = c; }
            if (v.y > m.y) { m.y = v.y; ay = c; }
            if (v.z > m.z) { m.z = v.z; az = c; }
            if (v.w > m.w) { m.w = v.w; aw = c; }
        }

        const int4 t = __ldg(reinterpret_cast<const int4*>(tgt) + p4);
        int i0 = t.x * CNUM + ax;  i0 = min(max(i0, 0), NBINS - 1);
        int i1 = t.y * CNUM + ay;  i1 = min(max(i1, 0), NBINS - 1);
        int i2 = t.z * CNUM + az;  i2 = min(max(i2, 0), NBINS - 1);
        int i3 = t.w * CNUM + aw;  i3 = min(max(i3, 0), NBINS - 1);
        atomicAdd(&hist[i0], 1);
        atomicAdd(&hist[i1], 1);
        atomicAdd(&hist[i2], 1);
        atomicAdd(&hist[i3], 1);
    }
    __syncthreads();

    for (int i = threadIdx.x; i < NBINS; i += blockDim.x) {
        const int v = hist[i];
        if (v) atomicAdd(&out[i], (float)v);
    }
}

extern "C" void kernel_launch(void* const* d_in, const int* in_sizes, int n_in,
                              void* d_out, int out_size)
{
    // Identify inputs by size (element counts or byte counts both accepted).
    const float* inp = nullptr;
    const int*   tgt = nullptr;
    for (int i = 0; i < n_in; i++) {
        const long long s = in_sizes[i];
        if (s == (long long)INP_ELEMS || s == (long long)INP_ELEMS * 4)
            inp = (const float*)d_in[i];
        else if (s == (long long)NPIX || s == (long long)NPIX * 4)
            tgt = (const int*)d_in[i];
    }
    if (!inp || !tgt) {
        int i_big = -1, i_second = -1;
        for (int i = 0; i < n_in; i++)
            if (i_big < 0 || in_sizes[i] > in_sizes[i_big]) i_big = i;
        for (int i = 0; i < n_in; i++) {
            if (i == i_big || in_sizes[i] <= 16) continue;
            if (i_second < 0 || in_sizes[i] > in_sizes[i_second]) i_second = i;
        }
        if (!inp && i_big >= 0)    inp = (const float*)d_in[i_big];
        if (!tgt && i_second >= 0) tgt = (const int*)d_in[i_second];
        if (!inp && n_in > 0) inp = (const float*)d_in[0];
        if (!tgt && n_in > 1) tgt = (const int*)d_in[1];
    }

    float* out = (float*)d_out;
    (void)out_size;

    zero_out_kernel<<<2, 256>>>(out);
    if (inp && tgt) {
        confmat_kernel<<<NP4 / 256, 256>>>(inp, tgt, out);   // 2048 blocks
    }
}

// round 8
// speedup vs baseline: 1.0649x; 1.0649x over previous
#include <cuda_runtime.h>

#define CNUM 19
#define HWD (512*512)
#define BATCH 8
#define NPIX (BATCH*HWD)
#define NP4 (NPIX/4)                 // 524,288 float4 groups
#define NP8 (NP4/2)                  // 262,144 pair-groups (8 pixels)
#define CH4 (HWD/4)                  // 65,536 = 2^16
#define NBINS (CNUM*CNUM)            // 361
#define INP_ELEMS (BATCH*CNUM*HWD)   // 39,845,888

__global__ void zero_out_kernel(float* __restrict__ out)
{
    int i = blockIdx.x * blockDim.x + threadIdx.x;
    if (i < NBINS) out[i] = 0.0f;
}

__global__ void __launch_bounds__(256)
confmat_kernel(const float* __restrict__ inp,
               const int*   __restrict__ tgt,
               float*       __restrict__ out)
{
    __shared__ int hist[NBINS];
    for (int i = threadIdx.x; i < NBINS; i += blockDim.x) hist[i] = 0;
    __syncthreads();

    const int stride = gridDim.x * blockDim.x;
    // Each iteration: 2 consecutive float4 groups = 8 pixels.
    for (int p2 = blockIdx.x * blockDim.x + threadIdx.x; p2 < NP8; p2 += stride) {
        const int g   = p2 * 2;            // even group index
        const int b   = g >> 16;           // g / CH4
        const int hw4 = g & (CH4 - 1);     // g % CH4 (even, so hw4+1 stays in-batch)
        const float4* base = reinterpret_cast<const float4*>(inp)
                             + (long long)b * (CNUM * CH4) + hw4;

        float4 ma = __ldg(&base[0]);
        float4 mb = __ldg(&base[1]);
        int ax = 0, ay = 0, az = 0, aw = 0;
        int bx = 0, by = 0, bz = 0, bw = 0;
        #pragma unroll
        for (int c = 1; c < CNUM; c++) {
            float4 va = __ldg(&base[c * CH4]);
            float4 vb = __ldg(&base[c * CH4 + 1]);
            if (va.x > ma.x) { ma.x = va.x; ax = c; }
            if (va.y > ma.y) { ma.y = va.y; ay = c; }
            if (va.z > ma.z) { ma.z = va.z; az = c; }
            if (va.w > ma.w) { ma.w = va.w; aw = c; }
            if (vb.x > mb.x) { mb.x = vb.x; bx = c; }
            if (vb.y > mb.y) { mb.y = vb.y; by = c; }
            if (vb.z > mb.z) { mb.z = vb.z; bz = c; }
            if (vb.w > mb.w) { mb.w = vb.w; bw = c; }
        }

        const int4 ta = __ldg(reinterpret_cast<const int4*>(tgt) + g);
        const int4 tb = __ldg(reinterpret_cast<const int4*>(tgt) + g + 1);
        int i0 = ta.x * CNUM + ax;  i0 = min(max(i0, 0), NBINS - 1);
        int i1 = ta.y * CNUM + ay;  i1 = min(max(i1, 0), NBINS - 1);
        int i2 = ta.z * CNUM + az;  i2 = min(max(i2, 0), NBINS - 1);
        int i3 = ta.w * CNUM + aw;  i3 = min(max(i3, 0), NBINS - 1);
        int i4 = tb.x * CNUM + bx;  i4 = min(max(i4, 0), NBINS - 1);
        int i5 = tb.y * CNUM + by;  i5 = min(max(i5, 0), NBINS - 1);
        int i6 = tb.z * CNUM + bz;  i6 = min(max(i6, 0), NBINS - 1);
        int i7 = tb.w * CNUM + bw;  i7 = min(max(i7, 0), NBINS - 1);
        atomicAdd(&hist[i0], 1);
        atomicAdd(&hist[i1], 1);
        atomicAdd(&hist[i2], 1);
        atomicAdd(&hist[i3], 1);
        atomicAdd(&hist[i4], 1);
        atomicAdd(&hist[i5], 1);
        atomicAdd(&hist[i6], 1);
        atomicAdd(&hist[i7], 1);
    }
    __syncthreads();

    for (int i = threadIdx.x; i < NBINS; i += blockDim.x) {
        const int v = hist[i];
        if (v) atomicAdd(&out[i], (float)v);
    }
}

extern "C" void kernel_launch(void* const* d_in, const int* in_sizes, int n_in,
                              void* d_out, int out_size)
{
    const float* inp = nullptr;
    const int*   tgt = nullptr;
    for (int i = 0; i < n_in; i++) {
        const long long s = in_sizes[i];
        if (s == (long long)INP_ELEMS || s == (long long)INP_ELEMS * 4)
            inp = (const float*)d_in[i];
        else if (s == (long long)NPIX || s == (long long)NPIX * 4)
            tgt = (const int*)d_in[i];
    }
    if (!inp || !tgt) {
        int i_big = -1, i_second = -1;
        for (int i = 0; i < n_in; i++)
            if (i_big < 0 || in_sizes[i] > in_sizes[i_big]) i_big = i;
        for (int i = 0; i < n_in; i++) {
            if (i == i_big || in_sizes[i] <= 16) continue;
            if (i_second < 0 || in_sizes[i] > in_sizes[i_second]) i_second = i;
        }
        if (!inp && i_big >= 0)    inp = (const float*)d_in[i_big];
        if (!tgt && i_second >= 0) tgt = (const int*)d_in[i_second];
        if (!inp && n_in > 0) inp = (const float*)d_in[0];
        if (!tgt && n_in > 1) tgt = (const int*)d_in[1];
    }

    float* out = (float*)d_out;
    (void)out_size;

    zero_out_kernel<<<2, 256>>>(out);
    if (inp && tgt) {
        confmat_kernel<<<592, 256>>>(inp, tgt, out);   // 4 CTAs/SM, single wave
    }
}